// round 5
// baseline (speedup 1.0000x reference)
#include <cuda_runtime.h>
#include <cuda_fp16.h>

#define TWO_PI 6.283185307179586f

typedef unsigned long long u64;

__device__ __forceinline__ float2 cmulf(float2 a, float2 b) {
    return make_float2(fmaf(a.x, b.x, -a.y * b.y), fmaf(a.x, b.y, a.y * b.x));
}
__device__ __forceinline__ float2 cadd(float2 a, float2 b) { return make_float2(a.x+b.x, a.y+b.y); }
__device__ __forceinline__ float2 csub(float2 a, float2 b) { return make_float2(a.x-b.x, a.y-b.y); }
__device__ __forceinline__ float2 mulc(float2 z, float cr, float ci) {
    return make_float2(fmaf(z.x, cr, -z.y * ci), fmaf(z.x, ci, z.y * cr));
}
__device__ __forceinline__ float2 h2f(__half2 h) { return __half22float2(h); }
__device__ __forceinline__ __half2 f2h(float2 f) { return __float22half2_rn(f); }

__device__ __forceinline__ u64 pk2(float lo, float hi) {
    u64 r; asm("mov.b64 %0, {%1, %2};" : "=l"(r) : "f"(lo), "f"(hi)); return r;
}
__device__ __forceinline__ u64 ffma2(u64 a, u64 b, u64 c) {
    u64 d; asm("fma.rn.f32x2 %0, %1, %2, %3;" : "=l"(d) : "l"(a), "l"(b), "l"(c)); return d;
}
__device__ __forceinline__ float2 upk2(u64 v) {
    float x, y; asm("mov.b64 {%0, %1}, %2;" : "=f"(x), "=f"(y) : "l"(v)); return make_float2(x, y);
}

// Frequency-domain scratch in fp16.
__device__ __half2 g_xf[16908288];   // (16*32) x 256 x 129
__device__ __half2 g_kf[33816576];   // (32*32) x 256 x 129
__device__ __half2 g_of[16908288];   // (16*32) x 256 x 129

// ---------------------------------------------------------------------------
// 4-point / 16-point register DFTs.
// ---------------------------------------------------------------------------
template <int SIGN>
__device__ __forceinline__ void dft4(float2 a, float2 b, float2 c, float2 d,
                                     float2& y0, float2& y1, float2& y2, float2& y3)
{
    float2 t0 = cadd(a, c), t1 = csub(a, c);
    float2 t2 = cadd(b, d), t3 = csub(b, d);
    float2 w3 = (SIGN < 0) ? make_float2(t3.y, -t3.x) : make_float2(-t3.y, t3.x);
    y0 = cadd(t0, t2); y2 = csub(t0, t2);
    y1 = cadd(t1, w3); y3 = csub(t1, w3);
}

template <int SIGN>
__device__ __forceinline__ void dft16(float2 r[16])
{
    const float C1 = 0.9238795325112867f;
    const float S1 = 0.3826834323650898f;
    const float C2 = 0.7071067811865476f;
    const float sg = (float)SIGN;

    float2 A[16];
#pragma unroll
    for (int n2 = 0; n2 < 4; n2++)
        dft4<SIGN>(r[n2], r[4 + n2], r[8 + n2], r[12 + n2],
                   A[n2 * 4 + 0], A[n2 * 4 + 1], A[n2 * 4 + 2], A[n2 * 4 + 3]);

    A[4 + 1]  = mulc(A[4 + 1],  C1,  sg * S1);
    A[4 + 2]  = mulc(A[4 + 2],  C2,  sg * C2);
    A[4 + 3]  = mulc(A[4 + 3],  S1,  sg * C1);
    A[8 + 1]  = mulc(A[8 + 1],  C2,  sg * C2);
    A[8 + 2]  = (SIGN < 0) ? make_float2(A[8 + 2].y, -A[8 + 2].x)
                           : make_float2(-A[8 + 2].y, A[8 + 2].x);
    A[8 + 3]  = mulc(A[8 + 3], -C2,  sg * C2);
    A[12 + 1] = mulc(A[12 + 1], S1,  sg * C1);
    A[12 + 2] = mulc(A[12 + 2], -C2, sg * C2);
    A[12 + 3] = mulc(A[12 + 3], -C1, -sg * S1);

#pragma unroll
    for (int k1 = 0; k1 < 4; k1++)
        dft4<SIGN>(A[k1], A[4 + k1], A[8 + k1], A[12 + k1],
                   r[k1], r[k1 + 4], r[k1 + 8], r[k1 + 12]);
}

__device__ __forceinline__ int zpad(int k) { return k + (k >> 4); }

// Shared-memory layout for the fused kernels (dynamic, 219136 bytes):
//   scratch : float2[8704]          (69632 B)  transpose scratch
//   table   : __half2[256*144]      (147456 B) freq rows table, stride 144
//   tw      : float2[256]           (2048 B)
#define SM_SCRATCH_F2  8704
#define SM_TABLE_OFF   69632
#define SM_TW_OFF      (69632 + 147456)
#define SM_TOTAL       219136
#define TSTR           144

// ---------------------------------------------------------------------------
// Fused forward 2-D rFFT: one image (256x256 f32) per block, 512 threads.
// Phase 1: packed row FFTs -> fp16 smem table [row][bin], bins 0..128.
// Phase 2: column FFTs over the table -> gmem fp16 (256 x 129).
// ---------------------------------------------------------------------------
__global__ void __launch_bounds__(512, 1) fwd2d_kernel(
    const float* __restrict__ in, __half2* __restrict__ out)
{
    extern __shared__ char smraw[];
    float2*  scratch = (float2*)smraw;
    __half2* table   = (__half2*)(smraw + SM_TABLE_OFF);
    float2*  tw      = (float2*)(smraw + SM_TW_OFF);

    const int t = threadIdx.x;
    if (t < 256) {
        float s, c;
        sincosf(-TWO_PI * (float)t / 256.0f, &s, &c);
        tw[t] = make_float2(c, s);
    }
    __syncthreads();

    // ---- Phase 1: row FFTs (pairs packed), half-warp private transposes ----
    {
        const int f = t >> 4, j = t & 15;      // f: 0..31
        const float* img = in + (size_t)blockIdx.x * 65536;
        float2* scr = scratch + f * 272;
#pragma unroll
        for (int pp = 0; pp < 4; pp++) {
            const int p = f + 32 * pp;          // row-pair 0..127
            const float* rp = img + p * 512;
            float2 r[16];
#pragma unroll
            for (int n1 = 0; n1 < 16; n1++)
                r[n1] = make_float2(rp[n1 * 16 + j], rp[256 + n1 * 16 + j]);
            dft16<-1>(r);
#pragma unroll
            for (int k1 = 0; k1 < 16; k1++) {
                if (k1) r[k1] = cmulf(r[k1], tw[j * k1]);
                scr[k1 * 17 + j] = r[k1];
            }
            __syncwarp();
            float2 d[16];
#pragma unroll
            for (int n2 = 0; n2 < 16; n2++) d[n2] = scr[j * 17 + n2];
            dft16<-1>(d);
            __syncwarp();
#pragma unroll
            for (int k2 = 0; k2 < 16; k2++) scr[zpad(j + 16 * k2)] = d[k2];
            __syncwarp();
            // unpack the two real spectra into the table
#pragma unroll
            for (int k2 = 0; k2 < 9; k2++) {
                int k = j + 16 * k2;
                if (k <= 128) {
                    float2 zk = scr[zpad(k)];
                    float2 zm = scr[zpad((256 - k) & 255)];
                    table[(2 * p) * TSTR + k] =
                        f2h(make_float2(0.5f * (zk.x + zm.x),  0.5f * (zk.y - zm.y)));
                    table[(2 * p + 1) * TSTR + k] =
                        f2h(make_float2(0.5f * (zk.y + zm.y), -0.5f * (zk.x - zm.x)));
                }
            }
            __syncwarp();
        }
    }
    __syncthreads();

    // ---- Phase 2: column FFTs, two 16-col groups at a time ----
    {
        const int c  = t & 15;
        const int j2 = (t >> 4) & 15;
        const int g  = t >> 8;                  // 0 or 1
        float2* scr2 = scratch + g * 4096;
        __half2* og = out + (size_t)blockIdx.x * 33024;
#pragma unroll
        for (int it = 0; it < 5; it++) {
            const int col = (it * 2 + g) * 16 + c;
            const bool valid = (col < 129);
            float2 r[16];
#pragma unroll
            for (int n1 = 0; n1 < 16; n1++)
                r[n1] = valid ? h2f(table[(n1 * 16 + j2) * TSTR + col])
                              : make_float2(0.f, 0.f);
            dft16<-1>(r);
#pragma unroll
            for (int k1 = 0; k1 < 16; k1++) {
                if (k1) r[k1] = cmulf(r[k1], tw[j2 * k1]);
                scr2[(k1 * 16 + j2) * 16 + c] = r[k1];
            }
            __syncthreads();
            float2 d[16];
#pragma unroll
            for (int n2 = 0; n2 < 16; n2++) d[n2] = scr2[(j2 * 16 + n2) * 16 + c];
            dft16<-1>(d);
            if (valid) {
#pragma unroll
                for (int k2 = 0; k2 < 16; k2++)
                    og[(j2 + 16 * k2) * 129 + col] = f2h(d[k2]);
            }
            __syncthreads();
        }
    }
}

// ---------------------------------------------------------------------------
// Fused inverse 2-D rFFT: one output image per block, 512 threads.
// Phase 1: inverse column FFTs gmem -> fp16 table. Phase 2: packed row
// inverse rFFTs table -> gmem f32 with 1/(H*W) scale.
// ---------------------------------------------------------------------------
__global__ void __launch_bounds__(512, 1) inv2d_kernel(
    const __half2* __restrict__ in, float* __restrict__ out)
{
    extern __shared__ char smraw[];
    float2*  scratch = (float2*)smraw;
    __half2* table   = (__half2*)(smraw + SM_TABLE_OFF);
    float2*  tw      = (float2*)(smraw + SM_TW_OFF);

    const int t = threadIdx.x;
    if (t < 256) {
        float s, c;
        sincosf(TWO_PI * (float)t / 256.0f, &s, &c);
        tw[t] = make_float2(c, s);
    }
    __syncthreads();

    // ---- Phase 1: inverse column FFTs into the table ----
    {
        const int c  = t & 15;
        const int j2 = (t >> 4) & 15;
        const int g  = t >> 8;
        float2* scr2 = scratch + g * 4096;
        const __half2* ig = in + (size_t)blockIdx.x * 33024;
#pragma unroll
        for (int it = 0; it < 5; it++) {
            const int col = (it * 2 + g) * 16 + c;
            const bool valid = (col < 129);
            float2 r[16];
#pragma unroll
            for (int n1 = 0; n1 < 16; n1++)
                r[n1] = valid ? h2f(ig[(n1 * 16 + j2) * 129 + col])
                              : make_float2(0.f, 0.f);
            dft16<1>(r);
#pragma unroll
            for (int k1 = 0; k1 < 16; k1++) {
                if (k1) r[k1] = cmulf(r[k1], tw[j2 * k1]);
                scr2[(k1 * 16 + j2) * 16 + c] = r[k1];
            }
            __syncthreads();
            float2 d[16];
#pragma unroll
            for (int n2 = 0; n2 < 16; n2++) d[n2] = scr2[(j2 * 16 + n2) * 16 + c];
            dft16<1>(d);
            if (valid) {
#pragma unroll
                for (int k2 = 0; k2 < 16; k2++)
                    table[(j2 + 16 * k2) * TSTR + col] = f2h(d[k2]);
            }
            __syncthreads();
        }
    }
    __syncthreads();

    // ---- Phase 2: packed inverse row rFFTs ----
    {
        const int f = t >> 4, j = t & 15;
        float* oimg = out + (size_t)blockIdx.x * 65536;
        float2* scr = scratch + f * 272;
        const float sc = 1.0f / 65536.0f;
#pragma unroll
        for (int pp = 0; pp < 4; pp++) {
            const int p = f + 32 * pp;
            const __half2* X0 = table + (2 * p) * TSTR;
            const __half2* X1 = table + (2 * p + 1) * TSTR;
            float2 r[16];
#pragma unroll
            for (int a = 0; a < 16; a++) {
                int k = a * 16 + j;
                float2 av, bv;
                if (k <= 128) { av = h2f(X0[k]); bv = h2f(X1[k]); }
                else {
                    float2 a0 = h2f(X0[256 - k]); av = make_float2(a0.x, -a0.y);
                    float2 b0 = h2f(X1[256 - k]); bv = make_float2(b0.x, -b0.y);
                }
                r[a] = make_float2(av.x - bv.y, av.y + bv.x);
            }
            dft16<1>(r);
#pragma unroll
            for (int k1 = 0; k1 < 16; k1++) {
                if (k1) r[k1] = cmulf(r[k1], tw[j * k1]);
                scr[k1 * 17 + j] = r[k1];
            }
            __syncwarp();
            float2 d[16];
#pragma unroll
            for (int n2 = 0; n2 < 16; n2++) d[n2] = scr[j * 17 + n2];
            dft16<1>(d);
            float* o = oimg + p * 512;
#pragma unroll
            for (int k2 = 0; k2 < 16; k2++) {
                int n = j + 16 * k2;
                o[n]       = d[k2].x * sc;
                o[256 + n] = d[k2].y * sc;
            }
            __syncwarp();
        }
    }
}

// ---------------------------------------------------------------------------
// Pointwise frequency contraction with packed f32x2 FMA (fp16 I/O, fp32 math).
// ---------------------------------------------------------------------------
__global__ void __launch_bounds__(256) pointwise_kernel(
    const __half2* __restrict__ xf, const __half2* __restrict__ kf,
    __half2* __restrict__ of)
{
    extern __shared__ float2 sm[];
    float2* xs = sm;          // 16 * 258 float2 (padded)
    float2* ks = sm + 4128;   // 32*32*8 float2
    const int t = threadIdx.x;
    const long f0 = (long)blockIdx.x * 8;

    for (int idx = t; idx < 4096; idx += 256) {
        int row = idx >> 3, fi = idx & 7;
        int b = row >> 5, cc = row & 31;
        xs[b * 258 + cc * 8 + fi] = h2f(xf[(size_t)row * 33024 + f0 + fi]);
    }
    for (int idx = t; idx < 8192; idx += 256) {
        ks[idx] = h2f(kf[(size_t)(idx >> 3) * 33024 + f0 + (idx & 7)]);
    }
    __syncthreads();

    const int fi = t & 7;
    const int g  = t >> 3;
    const int b0 = (g & 3) * 4;
    const int o0 = (g >> 2) * 4;

    u64 acc[4][4];
#pragma unroll
    for (int i = 0; i < 4; i++)
#pragma unroll
        for (int j = 0; j < 4; j++) acc[i][j] = 0ULL;

    for (int cc = 0; cc < 32; cc++) {
        u64 xa[4], xb[4], ka[4], kb[4];
#pragma unroll
        for (int i = 0; i < 4; i++) {
            float2 xv = xs[(b0 + i) * 258 + cc * 8 + fi];
            xa[i] = pk2(xv.x, xv.x);
            xb[i] = pk2(-xv.y, xv.y);
        }
#pragma unroll
        for (int j = 0; j < 4; j++) {
            float2 kv = ks[((o0 + j) * 32 + cc) * 8 + fi];
            ka[j] = pk2(kv.x, kv.y);
            kb[j] = pk2(kv.y, kv.x);
        }
#pragma unroll
        for (int i = 0; i < 4; i++)
#pragma unroll
            for (int j = 0; j < 4; j++) {
                acc[i][j] = ffma2(xa[i], ka[j], acc[i][j]);
                acc[i][j] = ffma2(xb[i], kb[j], acc[i][j]);
            }
    }

#pragma unroll
    for (int i = 0; i < 4; i++)
#pragma unroll
        for (int j = 0; j < 4; j++)
            of[(size_t)((b0 + i) * 32 + (o0 + j)) * 33024 + f0 + fi] = f2h(upk2(acc[i][j]));
}

// ---------------------------------------------------------------------------
extern "C" void kernel_launch(void* const* d_in, const int* in_sizes, int n_in,
                              void* d_out, int out_size)
{
    const float* x = (const float*)d_in[0];   // (16,32,256,256)
    const float* w = (const float*)d_in[1];   // (32,32,256,256)
    float* out = (float*)d_out;               // (16,32,256,256)

    __half2 *pxf, *pkf, *pof;
    cudaGetSymbolAddress((void**)&pxf, g_xf);
    cudaGetSymbolAddress((void**)&pkf, g_kf);
    cudaGetSymbolAddress((void**)&pof, g_of);

    cudaFuncSetAttribute(fwd2d_kernel,
                         cudaFuncAttributeMaxDynamicSharedMemorySize, SM_TOTAL);
    cudaFuncSetAttribute(inv2d_kernel,
                         cudaFuncAttributeMaxDynamicSharedMemorySize, SM_TOTAL);
    cudaFuncSetAttribute(pointwise_kernel,
                         cudaFuncAttributeMaxDynamicSharedMemorySize, 98560);

    // Fused forward 2-D rFFT: one image per block.
    fwd2d_kernel<<<512, 512, SM_TOTAL>>>(x, pxf);
    fwd2d_kernel<<<1024, 512, SM_TOTAL>>>(w, pkf);

    // Per-bin channel contraction.
    pointwise_kernel<<<4128, 256, 98560>>>(pxf, pkf, pof);

    // Fused inverse 2-D rFFT: one output image per block.
    inv2d_kernel<<<512, 512, SM_TOTAL>>>(pof, out);
}

// round 6
// speedup vs baseline: 1.0440x; 1.0440x over previous
#include <cuda_runtime.h>
#include <cuda_fp16.h>
#include <mma.h>

#define TWO_PI 6.283185307179586f

using namespace nvcuda;

__device__ __forceinline__ float2 cmulf(float2 a, float2 b) {
    return make_float2(fmaf(a.x, b.x, -a.y * b.y), fmaf(a.x, b.y, a.y * b.x));
}
__device__ __forceinline__ float2 cadd(float2 a, float2 b) { return make_float2(a.x+b.x, a.y+b.y); }
__device__ __forceinline__ float2 csub(float2 a, float2 b) { return make_float2(a.x-b.x, a.y-b.y); }
__device__ __forceinline__ float2 mulc(float2 z, float cr, float ci) {
    return make_float2(fmaf(z.x, cr, -z.y * ci), fmaf(z.x, ci, z.y * cr));
}
__device__ __forceinline__ float2 h2f(__half2 h) { return __half22float2(h); }
__device__ __forceinline__ __half2 f2h(float2 f) { return __float22half2_rn(f); }

// Frequency-domain scratch in fp16.
__device__ __half2 g_xf[16908288];   // (16*32) x 256 x 129
__device__ __half2 g_kf[33816576];   // (32*32) x 256 x 129
__device__ __half2 g_of[16908288];   // (16*32) x 256 x 129

// ---------------------------------------------------------------------------
// 4-point / 16-point register DFTs.
// ---------------------------------------------------------------------------
template <int SIGN>
__device__ __forceinline__ void dft4(float2 a, float2 b, float2 c, float2 d,
                                     float2& y0, float2& y1, float2& y2, float2& y3)
{
    float2 t0 = cadd(a, c), t1 = csub(a, c);
    float2 t2 = cadd(b, d), t3 = csub(b, d);
    float2 w3 = (SIGN < 0) ? make_float2(t3.y, -t3.x) : make_float2(-t3.y, t3.x);
    y0 = cadd(t0, t2); y2 = csub(t0, t2);
    y1 = cadd(t1, w3); y3 = csub(t1, w3);
}

template <int SIGN>
__device__ __forceinline__ void dft16(float2 r[16])
{
    const float C1 = 0.9238795325112867f;
    const float S1 = 0.3826834323650898f;
    const float C2 = 0.7071067811865476f;
    const float sg = (float)SIGN;

    float2 A[16];
#pragma unroll
    for (int n2 = 0; n2 < 4; n2++)
        dft4<SIGN>(r[n2], r[4 + n2], r[8 + n2], r[12 + n2],
                   A[n2 * 4 + 0], A[n2 * 4 + 1], A[n2 * 4 + 2], A[n2 * 4 + 3]);

    A[4 + 1]  = mulc(A[4 + 1],  C1,  sg * S1);
    A[4 + 2]  = mulc(A[4 + 2],  C2,  sg * C2);
    A[4 + 3]  = mulc(A[4 + 3],  S1,  sg * C1);
    A[8 + 1]  = mulc(A[8 + 1],  C2,  sg * C2);
    A[8 + 2]  = (SIGN < 0) ? make_float2(A[8 + 2].y, -A[8 + 2].x)
                           : make_float2(-A[8 + 2].y, A[8 + 2].x);
    A[8 + 3]  = mulc(A[8 + 3], -C2,  sg * C2);
    A[12 + 1] = mulc(A[12 + 1], S1,  sg * C1);
    A[12 + 2] = mulc(A[12 + 2], -C2, sg * C2);
    A[12 + 3] = mulc(A[12 + 3], -C1, -sg * S1);

#pragma unroll
    for (int k1 = 0; k1 < 4; k1++)
        dft4<SIGN>(A[k1], A[4 + k1], A[8 + k1], A[12 + k1],
                   r[k1], r[k1 + 4], r[k1 + 8], r[k1 + 12]);
}

__device__ __forceinline__ int zpad(int k) { return k + (k >> 4); }

// ---------------------------------------------------------------------------
// Forward real FFT along W: 16 packed row-pairs per block, 16 threads per FFT.
// ---------------------------------------------------------------------------
__global__ void __launch_bounds__(256) rfft_rows_kernel(
    const float* __restrict__ in, __half2* __restrict__ out)
{
    __shared__ float2 tr[16][272];
    __shared__ float2 tw[256];
    const int t = threadIdx.x;
    const int f = t >> 4, j = t & 15;

    {
        float s, c;
        sincosf(-TWO_PI * (float)t / 256.0f, &s, &c);
        tw[t] = make_float2(c, s);
    }

    const long p = (long)blockIdx.x * 16 + f;
    const float* rp = in + p * 512;

    float2 r[16];
#pragma unroll
    for (int n1 = 0; n1 < 16; n1++)
        r[n1] = make_float2(rp[n1 * 16 + j], rp[256 + n1 * 16 + j]);

    dft16<-1>(r);
    __syncthreads();

#pragma unroll
    for (int k1 = 0; k1 < 16; k1++) {
        if (k1) r[k1] = cmulf(r[k1], tw[j * k1]);
        tr[f][k1 * 17 + j] = r[k1];
    }
    __syncthreads();

    float2 d[16];
#pragma unroll
    for (int n2 = 0; n2 < 16; n2++)
        d[n2] = tr[f][j * 17 + n2];

    dft16<-1>(d);
    __syncthreads();

#pragma unroll
    for (int k2 = 0; k2 < 16; k2++)
        tr[f][zpad(j + 16 * k2)] = d[k2];
    __syncthreads();

    __half2* o = out + p * 258;
#pragma unroll
    for (int k2 = 0; k2 < 9; k2++) {
        int k = j + 16 * k2;
        if (k <= 128) {
            float2 zk = tr[f][zpad(k)];
            float2 zm = tr[f][zpad((256 - k) & 255)];
            o[k]       = f2h(make_float2(0.5f * (zk.x + zm.x),  0.5f * (zk.y - zm.y)));
            o[129 + k] = f2h(make_float2(0.5f * (zk.y + zm.y), -0.5f * (zk.x - zm.x)));
        }
    }
}

// ---------------------------------------------------------------------------
// Complex FFT along H: 16x16 register Cooley-Tukey, 16 columns per block.
// ---------------------------------------------------------------------------
template <int SIGN>
__global__ void __launch_bounds__(256) fft_cols_kernel(__half2* __restrict__ data)
{
    __shared__ float2 tr[4096];
    __shared__ float2 tw[256];
    const int t = threadIdx.x;
    const int c = t & 15, j = t >> 4;

    {
        float s, cc;
        sincosf((float)SIGN * TWO_PI * (float)t / 256.0f, &s, &cc);
        tw[t] = make_float2(cc, s);
    }

    __half2* img = data + (size_t)blockIdx.y * 33024;
    const int col = blockIdx.x * 16 + c;
    const bool valid = (col < 129);

    float2 r[16];
#pragma unroll
    for (int n1 = 0; n1 < 16; n1++)
        r[n1] = valid ? h2f(img[(n1 * 16 + j) * 129 + col]) : make_float2(0.f, 0.f);

    dft16<SIGN>(r);
    __syncthreads();

#pragma unroll
    for (int k1 = 0; k1 < 16; k1++) {
        if (k1) r[k1] = cmulf(r[k1], tw[j * k1]);
        tr[(k1 * 16 + j) * 16 + c] = r[k1];
    }
    __syncthreads();

    float2 d[16];
#pragma unroll
    for (int n2 = 0; n2 < 16; n2++)
        d[n2] = tr[(j * 16 + n2) * 16 + c];

    dft16<SIGN>(d);

    if (valid) {
#pragma unroll
        for (int k2 = 0; k2 < 16; k2++)
            img[(j + 16 * k2) * 129 + col] = f2h(d[k2]);
    }
}

// ---------------------------------------------------------------------------
// Pointwise frequency contraction with tensor cores (WMMA m16n16k16,
// fp16 inputs / fp32 accumulate). 8 bins per block, warp <-> bin.
//
// Per bin f: OUT(16b x 32o) = X(16b x 32c) * K^T, complex:
//   out_r = Xr*Kr + Xi*(-Ki),  out_i = Xr*Ki + Xi*Kr
//
// Dynamic smem (bytes):
//   [0      ) sxr  8*16*32 half   (8192 B)
//   [8192   ) sxi                 (8192 B)
//   [16384  ) skr  8*32*32 half  (16384 B)
//   [32768  ) ski                (16384 B)
//   [49152  ) skn (-Ki)          (16384 B)
//   [65536  ) sor  8*16*32 float (16384 B)
//   [81920  ) soi                (16384 B)
//   total 98304 B
// ---------------------------------------------------------------------------
#define PW_SMEM 98304

__global__ void __launch_bounds__(256) pointwise_kernel(
    const __half2* __restrict__ xf, const __half2* __restrict__ kf,
    __half2* __restrict__ of)
{
    extern __shared__ char pwsm[];
    __half* sxr = (__half*)pwsm;               // [8][16][32]
    __half* sxi = sxr + 4096;
    __half* skr = sxi + 4096;                  // [8][32][32]
    __half* ski = skr + 8192;
    __half* skn = ski + 8192;
    float*  sor = (float*)(pwsm + 65536);      // [8][16][32]
    float*  soi = sor + 4096;

    const int t = threadIdx.x;
    const long f0 = (long)blockIdx.x * 8;

    // Stage X: rows = b*32+c (512 rows), 8 consecutive bins.
    for (int idx = t; idx < 4096; idx += 256) {
        int row = idx >> 3, fi = idx & 7;
        __half2 v = xf[(size_t)row * 33024 + f0 + fi];
        int b = row >> 5, c = row & 31;
        sxr[fi * 512 + b * 32 + c] = __low2half(v);
        sxi[fi * 512 + b * 32 + c] = __high2half(v);
    }
    // Stage K: rows = o*32+c (1024 rows).
    for (int idx = t; idx < 8192; idx += 256) {
        int row = idx >> 3, fi = idx & 7;
        __half2 v = kf[(size_t)row * 33024 + f0 + fi];
        int o = row >> 5, c = row & 31;
        __half re = __low2half(v), im = __high2half(v);
        skr[fi * 1024 + o * 32 + c] = re;
        ski[fi * 1024 + o * 32 + c] = im;
        skn[fi * 1024 + o * 32 + c] = __hneg(im);
    }
    __syncthreads();

    // Each warp computes one bin's (16 x 32) complex GEMM.
    {
        const int fi = t >> 5;
        const __half* xr = sxr + fi * 512;
        const __half* xi = sxi + fi * 512;
        const __half* kr = skr + fi * 1024;
        const __half* ki = ski + fi * 1024;
        const __half* kn = skn + fi * 1024;

#pragma unroll
        for (int nt = 0; nt < 2; nt++) {
            wmma::fragment<wmma::accumulator, 16, 16, 16, float> accr, acci;
            wmma::fill_fragment(accr, 0.0f);
            wmma::fill_fragment(acci, 0.0f);
#pragma unroll
            for (int kt = 0; kt < 2; kt++) {
                wmma::fragment<wmma::matrix_a, 16, 16, 16, __half, wmma::row_major> ar, ai;
                wmma::load_matrix_sync(ar, xr + kt * 16, 32);
                wmma::load_matrix_sync(ai, xi + kt * 16, 32);
                // B tile (col_major view of K stored row-major (o,c)):
                // B[c][o] = K[o][c]; tile origin (c0 = kt*16, o0 = nt*16).
                const int koff = (nt * 16) * 32 + kt * 16;
                wmma::fragment<wmma::matrix_b, 16, 16, 16, __half, wmma::col_major> br, bi, bn;
                wmma::load_matrix_sync(br, kr + koff, 32);
                wmma::load_matrix_sync(bi, ki + koff, 32);
                wmma::load_matrix_sync(bn, kn + koff, 32);
                wmma::mma_sync(accr, ar, br, accr);
                wmma::mma_sync(accr, ai, bn, accr);
                wmma::mma_sync(acci, ar, bi, acci);
                wmma::mma_sync(acci, ai, br, acci);
            }
            wmma::store_matrix_sync(sor + fi * 512 + nt * 16, accr, 32, wmma::mem_row_major);
            wmma::store_matrix_sync(soi + fi * 512 + nt * 16, acci, 32, wmma::mem_row_major);
        }
    }
    __syncthreads();

    // Write out: rows = b*32+o (512 rows), 8 consecutive bins.
    for (int idx = t; idx < 4096; idx += 256) {
        int row = idx >> 3, fi = idx & 7;
        int b = row >> 5, o = row & 31;
        float re = sor[fi * 512 + b * 32 + o];
        float im = soi[fi * 512 + b * 32 + o];
        of[(size_t)row * 33024 + f0 + fi] = f2h(make_float2(re, im));
    }
}

// ---------------------------------------------------------------------------
// Inverse real FFT along W: 16 row-pairs per block, register 16x16 FFT.
// ---------------------------------------------------------------------------
__global__ void __launch_bounds__(256) irfft_rows_kernel(
    const __half2* __restrict__ in, float* __restrict__ out)
{
    __shared__ float2 tr[16][272];
    __shared__ float2 tw[256];
    const int t = threadIdx.x;
    const int f = t >> 4, j = t & 15;

    {
        float s, c;
        sincosf(TWO_PI * (float)t / 256.0f, &s, &c);
        tw[t] = make_float2(c, s);
    }

    const long p = (long)blockIdx.x * 16 + f;
    const __half2* X0 = in + p * 258;
    const __half2* X1 = X0 + 129;

    float2 r[16];
#pragma unroll
    for (int a = 0; a < 16; a++) {
        int k = a * 16 + j;
        float2 av, bv;
        if (k <= 128) { av = h2f(X0[k]); bv = h2f(X1[k]); }
        else {
            float2 a0 = h2f(X0[256 - k]); av = make_float2(a0.x, -a0.y);
            float2 b0 = h2f(X1[256 - k]); bv = make_float2(b0.x, -b0.y);
        }
        r[a] = make_float2(av.x - bv.y, av.y + bv.x);
    }

    dft16<1>(r);
    __syncthreads();

#pragma unroll
    for (int k1 = 0; k1 < 16; k1++) {
        if (k1) r[k1] = cmulf(r[k1], tw[j * k1]);
        tr[f][k1 * 17 + j] = r[k1];
    }
    __syncthreads();

    float2 d[16];
#pragma unroll
    for (int n2 = 0; n2 < 16; n2++)
        d[n2] = tr[f][j * 17 + n2];

    dft16<1>(d);

    const float sc = 1.0f / 65536.0f;
    float* o = out + p * 512;
#pragma unroll
    for (int k2 = 0; k2 < 16; k2++) {
        int n = j + 16 * k2;
        o[n]       = d[k2].x * sc;
        o[256 + n] = d[k2].y * sc;
    }
}

// ---------------------------------------------------------------------------
extern "C" void kernel_launch(void* const* d_in, const int* in_sizes, int n_in,
                              void* d_out, int out_size)
{
    const float* x = (const float*)d_in[0];   // (16,32,256,256)
    const float* w = (const float*)d_in[1];   // (32,32,256,256)
    float* out = (float*)d_out;               // (16,32,256,256)

    __half2 *pxf, *pkf, *pof;
    cudaGetSymbolAddress((void**)&pxf, g_xf);
    cudaGetSymbolAddress((void**)&pkf, g_kf);
    cudaGetSymbolAddress((void**)&pof, g_of);

    cudaFuncSetAttribute(pointwise_kernel,
                         cudaFuncAttributeMaxDynamicSharedMemorySize, PW_SMEM);

    // Forward rFFT along W (packed pairs, 16 pairs per block).
    rfft_rows_kernel<<<4096, 256>>>(x, pxf);
    rfft_rows_kernel<<<8192, 256>>>(w, pkf);

    // Forward FFT along H.
    fft_cols_kernel<-1><<<dim3(9, 512), 256>>>(pxf);
    fft_cols_kernel<-1><<<dim3(9, 1024), 256>>>(pkf);

    // Per-bin channel contraction on tensor cores.
    pointwise_kernel<<<4128, 256, PW_SMEM>>>(pxf, pkf, pof);

    // Inverse FFT along H + inverse rFFT along W.
    fft_cols_kernel<1><<<dim3(9, 512), 256>>>(pof);
    irfft_rows_kernel<<<4096, 256>>>(pof, out);
}

// round 8
// speedup vs baseline: 1.2256x; 1.1739x over previous
#include <cuda_runtime.h>
#include <cuda_fp16.h>
#include <mma.h>

#define TWO_PI 6.283185307179586f

using namespace nvcuda;

__device__ __forceinline__ float2 cmulf(float2 a, float2 b) {
    return make_float2(fmaf(a.x, b.x, -a.y * b.y), fmaf(a.x, b.y, a.y * b.x));
}
__device__ __forceinline__ float2 cadd(float2 a, float2 b) { return make_float2(a.x+b.x, a.y+b.y); }
__device__ __forceinline__ float2 csub(float2 a, float2 b) { return make_float2(a.x-b.x, a.y-b.y); }
__device__ __forceinline__ float2 mulc(float2 z, float cr, float ci) {
    return make_float2(fmaf(z.x, cr, -z.y * ci), fmaf(z.x, ci, z.y * cr));
}
__device__ __forceinline__ float2 h2f(__half2 h) { return __half22float2(h); }
__device__ __forceinline__ __half2 f2h(float2 f) { return __float22half2_rn(f); }

// Frequency-domain scratch in fp16.
__device__ __half2 g_xf[16908288];   // (16*32) x 256 x 129
__device__ __half2 g_kf[33816576];   // (32*32) x 256 x 129
__device__ __half2 g_of[16908288];   // (16*32) x 256 x 129

// ---------------------------------------------------------------------------
// 4-point / 16-point register DFTs.
// ---------------------------------------------------------------------------
template <int SIGN>
__device__ __forceinline__ void dft4(float2 a, float2 b, float2 c, float2 d,
                                     float2& y0, float2& y1, float2& y2, float2& y3)
{
    float2 t0 = cadd(a, c), t1 = csub(a, c);
    float2 t2 = cadd(b, d), t3 = csub(b, d);
    float2 w3 = (SIGN < 0) ? make_float2(t3.y, -t3.x) : make_float2(-t3.y, t3.x);
    y0 = cadd(t0, t2); y2 = csub(t0, t2);
    y1 = cadd(t1, w3); y3 = csub(t1, w3);
}

template <int SIGN>
__device__ __forceinline__ void dft16(float2 r[16])
{
    const float C1 = 0.9238795325112867f;
    const float S1 = 0.3826834323650898f;
    const float C2 = 0.7071067811865476f;
    const float sg = (float)SIGN;

    float2 A[16];
#pragma unroll
    for (int n2 = 0; n2 < 4; n2++)
        dft4<SIGN>(r[n2], r[4 + n2], r[8 + n2], r[12 + n2],
                   A[n2 * 4 + 0], A[n2 * 4 + 1], A[n2 * 4 + 2], A[n2 * 4 + 3]);

    A[4 + 1]  = mulc(A[4 + 1],  C1,  sg * S1);
    A[4 + 2]  = mulc(A[4 + 2],  C2,  sg * C2);
    A[4 + 3]  = mulc(A[4 + 3],  S1,  sg * C1);
    A[8 + 1]  = mulc(A[8 + 1],  C2,  sg * C2);
    A[8 + 2]  = (SIGN < 0) ? make_float2(A[8 + 2].y, -A[8 + 2].x)
                           : make_float2(-A[8 + 2].y, A[8 + 2].x);
    A[8 + 3]  = mulc(A[8 + 3], -C2,  sg * C2);
    A[12 + 1] = mulc(A[12 + 1], S1,  sg * C1);
    A[12 + 2] = mulc(A[12 + 2], -C2, sg * C2);
    A[12 + 3] = mulc(A[12 + 3], -C1, -sg * S1);

#pragma unroll
    for (int k1 = 0; k1 < 4; k1++)
        dft4<SIGN>(A[k1], A[4 + k1], A[8 + k1], A[12 + k1],
                   r[k1], r[k1 + 4], r[k1 + 8], r[k1 + 12]);
}

__device__ __forceinline__ int zpad(int k) { return k + (k >> 4); }

// ---------------------------------------------------------------------------
// Forward real FFT along W: 16 packed row-pairs per block, 16 threads per FFT.
// ---------------------------------------------------------------------------
__global__ void __launch_bounds__(256) rfft_rows_kernel(
    const float* __restrict__ in, __half2* __restrict__ out)
{
    __shared__ float2 tr[16][272];
    __shared__ float2 tw[256];
    const int t = threadIdx.x;
    const int f = t >> 4, j = t & 15;

    {
        float s, c;
        sincosf(-TWO_PI * (float)t / 256.0f, &s, &c);
        tw[t] = make_float2(c, s);
    }

    const long p = (long)blockIdx.x * 16 + f;
    const float* rp = in + p * 512;

    float2 r[16];
#pragma unroll
    for (int n1 = 0; n1 < 16; n1++)
        r[n1] = make_float2(rp[n1 * 16 + j], rp[256 + n1 * 16 + j]);

    dft16<-1>(r);
    __syncthreads();

#pragma unroll
    for (int k1 = 0; k1 < 16; k1++) {
        if (k1) r[k1] = cmulf(r[k1], tw[j * k1]);
        tr[f][k1 * 17 + j] = r[k1];
    }
    __syncthreads();

    float2 d[16];
#pragma unroll
    for (int n2 = 0; n2 < 16; n2++)
        d[n2] = tr[f][j * 17 + n2];

    dft16<-1>(d);
    __syncthreads();

#pragma unroll
    for (int k2 = 0; k2 < 16; k2++)
        tr[f][zpad(j + 16 * k2)] = d[k2];
    __syncthreads();

    __half2* o = out + p * 258;
#pragma unroll
    for (int k2 = 0; k2 < 9; k2++) {
        int k = j + 16 * k2;
        if (k <= 128) {
            float2 zk = tr[f][zpad(k)];
            float2 zm = tr[f][zpad((256 - k) & 255)];
            o[k]       = f2h(make_float2(0.5f * (zk.x + zm.x),  0.5f * (zk.y - zm.y)));
            o[129 + k] = f2h(make_float2(0.5f * (zk.y + zm.y), -0.5f * (zk.x - zm.x)));
        }
    }
}

// ---------------------------------------------------------------------------
// Complex FFT along H: 16x16 register Cooley-Tukey, 16 columns per block.
// ---------------------------------------------------------------------------
template <int SIGN>
__global__ void __launch_bounds__(256) fft_cols_kernel(__half2* __restrict__ data)
{
    __shared__ float2 tr[4096];
    __shared__ float2 tw[256];
    const int t = threadIdx.x;
    const int c = t & 15, j = t >> 4;

    {
        float s, cc;
        sincosf((float)SIGN * TWO_PI * (float)t / 256.0f, &s, &cc);
        tw[t] = make_float2(cc, s);
    }

    __half2* img = data + (size_t)blockIdx.y * 33024;
    const int col = blockIdx.x * 16 + c;
    const bool valid = (col < 129);

    float2 r[16];
#pragma unroll
    for (int n1 = 0; n1 < 16; n1++)
        r[n1] = valid ? h2f(img[(n1 * 16 + j) * 129 + col]) : make_float2(0.f, 0.f);

    dft16<SIGN>(r);
    __syncthreads();

#pragma unroll
    for (int k1 = 0; k1 < 16; k1++) {
        if (k1) r[k1] = cmulf(r[k1], tw[j * k1]);
        tr[(k1 * 16 + j) * 16 + c] = r[k1];
    }
    __syncthreads();

    float2 d[16];
#pragma unroll
    for (int n2 = 0; n2 < 16; n2++)
        d[n2] = tr[(j * 16 + n2) * 16 + c];

    dft16<SIGN>(d);

    if (valid) {
#pragma unroll
        for (int k2 = 0; k2 < 16; k2++)
            img[(j + 16 * k2) * 129 + col] = f2h(d[k2]);
    }
}

// ---------------------------------------------------------------------------
// Pointwise frequency contraction on tensor cores (WMMA m16n16k16, fp16 in /
// fp32 accumulate). 8 bins per block, warp <-> bin.
//
// Per bin f: OUT(16b x 32o) = X(16b x 32c) * K(32o x 32c)^T, complex via
//   out_r = Xr*Kr + (-Xi)*Ki,  out_i = Xr*Ki + Xi*Kr   (-Xi negated in regs)
//
// Padded smem layout (halves / floats), all bases & strides 16B-aligned and
// strides == 4 words mod 32 -> <=2-way bank conflicts in staging:
//   sxr/sxi : per-bin stride 648 halves (16 rows x ldm 40)
//   skr/ski : per-bin stride 1288 halves (32 rows x ldm 40)
//   sor/soi : per-bin stride 644 floats (16 rows x ldm 40)
// ---------------------------------------------------------------------------
#define XSTR 648
#define KSTR 1288
#define OSTR 644
#define OFF_SXI (8 * XSTR)                 // halves
#define OFF_SKR (16 * XSTR)
#define OFF_SKI (16 * XSTR + 8 * KSTR)
#define OFF_SOR ((16 * XSTR + 16 * KSTR) * 2)  // bytes
#define OFF_SOI (OFF_SOR + 8 * OSTR * 4)
#define PW_SMEM (OFF_SOI + 8 * OSTR * 4)       // 101824 B

__global__ void __launch_bounds__(256) pointwise_kernel(
    const __half2* __restrict__ xf, const __half2* __restrict__ kf,
    __half2* __restrict__ of)
{
    extern __shared__ char pwsm[];
    __half* sxr = (__half*)pwsm;
    __half* sxi = sxr + OFF_SXI;
    __half* skr = sxr + OFF_SKR;
    __half* ski = sxr + OFF_SKI;
    float*  sor = (float*)(pwsm + OFF_SOR);
    float*  soi = (float*)(pwsm + OFF_SOI);

    const int t = threadIdx.x;
    const long f0 = (long)blockIdx.x * 8;

    // Stage X: rows = b*32+c (512 rows), 8 consecutive bins (32B/row chunk).
    for (int idx = t; idx < 4096; idx += 256) {
        int row = idx >> 3, fi = idx & 7;
        __half2 v = xf[(size_t)row * 33024 + f0 + fi];
        int b = row >> 5, c = row & 31;
        int a = fi * XSTR + b * 40 + c;
        sxr[a] = __low2half(v);
        sxi[a] = __high2half(v);
    }
    // Stage K: rows = o*32+c (1024 rows).
    for (int idx = t; idx < 8192; idx += 256) {
        int row = idx >> 3, fi = idx & 7;
        __half2 v = kf[(size_t)row * 33024 + f0 + fi];
        int o = row >> 5, c = row & 31;
        int a = fi * KSTR + o * 40 + c;
        skr[a] = __low2half(v);
        ski[a] = __high2half(v);
    }
    __syncthreads();

    // Each warp computes one bin's (16 x 32) complex GEMM.
    {
        const int fi = t >> 5;
        const __half* xr = sxr + fi * XSTR;
        const __half* xi = sxi + fi * XSTR;
        const __half* kr = skr + fi * KSTR;
        const __half* ki = ski + fi * KSTR;

        // Hoisted A fragments (re, im, -im) for both k-tiles.
        wmma::fragment<wmma::matrix_a, 16, 16, 16, __half, wmma::row_major> ar[2], ai[2], an[2];
#pragma unroll
        for (int kt = 0; kt < 2; kt++) {
            wmma::load_matrix_sync(ar[kt], xr + kt * 16, 40);
            wmma::load_matrix_sync(ai[kt], xi + kt * 16, 40);
#pragma unroll
            for (int e = 0; e < ai[kt].num_elements; e++)
                an[kt].x[e] = __hneg(ai[kt].x[e]);
        }

#pragma unroll
        for (int nt = 0; nt < 2; nt++) {
            wmma::fragment<wmma::accumulator, 16, 16, 16, float> accr, acci;
            wmma::fill_fragment(accr, 0.0f);
            wmma::fill_fragment(acci, 0.0f);
#pragma unroll
            for (int kt = 0; kt < 2; kt++) {
                // B tile: col_major view of K stored row-major (o,c), ldm 40.
                const int koff = (nt * 16) * 40 + kt * 16;
                wmma::fragment<wmma::matrix_b, 16, 16, 16, __half, wmma::col_major> br, bi;
                wmma::load_matrix_sync(br, kr + koff, 40);
                wmma::load_matrix_sync(bi, ki + koff, 40);
                wmma::mma_sync(accr, ar[kt], br, accr);
                wmma::mma_sync(accr, an[kt], bi, accr);
                wmma::mma_sync(acci, ar[kt], bi, acci);
                wmma::mma_sync(acci, ai[kt], br, acci);
            }
            wmma::store_matrix_sync(sor + fi * OSTR + nt * 16, accr, 40, wmma::mem_row_major);
            wmma::store_matrix_sync(soi + fi * OSTR + nt * 16, acci, 40, wmma::mem_row_major);
        }
    }
    __syncthreads();

    // Write out: rows = b*32+o (512 rows), 8 consecutive bins.
    for (int idx = t; idx < 4096; idx += 256) {
        int row = idx >> 3, fi = idx & 7;
        int b = row >> 5, o = row & 31;
        float re = sor[fi * OSTR + b * 40 + o];
        float im = soi[fi * OSTR + b * 40 + o];
        of[(size_t)row * 33024 + f0 + fi] = f2h(make_float2(re, im));
    }
}

// ---------------------------------------------------------------------------
// Inverse real FFT along W: 16 row-pairs per block, register 16x16 FFT.
// ---------------------------------------------------------------------------
__global__ void __launch_bounds__(256) irfft_rows_kernel(
    const __half2* __restrict__ in, float* __restrict__ out)
{
    __shared__ float2 tr[16][272];
    __shared__ float2 tw[256];
    const int t = threadIdx.x;
    const int f = t >> 4, j = t & 15;

    {
        float s, c;
        sincosf(TWO_PI * (float)t / 256.0f, &s, &c);
        tw[t] = make_float2(c, s);
    }

    const long p = (long)blockIdx.x * 16 + f;
    const __half2* X0 = in + p * 258;
    const __half2* X1 = X0 + 129;

    float2 r[16];
#pragma unroll
    for (int a = 0; a < 16; a++) {
        int k = a * 16 + j;
        float2 av, bv;
        if (k <= 128) { av = h2f(X0[k]); bv = h2f(X1[k]); }
        else {
            float2 a0 = h2f(X0[256 - k]); av = make_float2(a0.x, -a0.y);
            float2 b0 = h2f(X1[256 - k]); bv = make_float2(b0.x, -b0.y);
        }
        r[a] = make_float2(av.x - bv.y, av.y + bv.x);
    }

    dft16<1>(r);
    __syncthreads();

#pragma unroll
    for (int k1 = 0; k1 < 16; k1++) {
        if (k1) r[k1] = cmulf(r[k1], tw[j * k1]);
        tr[f][k1 * 17 + j] = r[k1];
    }
    __syncthreads();

    float2 d[16];
#pragma unroll
    for (int n2 = 0; n2 < 16; n2++)
        d[n2] = tr[f][j * 17 + n2];

    dft16<1>(d);

    const float sc = 1.0f / 65536.0f;
    float* o = out + p * 512;
#pragma unroll
    for (int k2 = 0; k2 < 16; k2++) {
        int n = j + 16 * k2;
        o[n]       = d[k2].x * sc;
        o[256 + n] = d[k2].y * sc;
    }
}

// ---------------------------------------------------------------------------
extern "C" void kernel_launch(void* const* d_in, const int* in_sizes, int n_in,
                              void* d_out, int out_size)
{
    const float* x = (const float*)d_in[0];   // (16,32,256,256)
    const float* w = (const float*)d_in[1];   // (32,32,256,256)
    float* out = (float*)d_out;               // (16,32,256,256)

    __half2 *pxf, *pkf, *pof;
    cudaGetSymbolAddress((void**)&pxf, g_xf);
    cudaGetSymbolAddress((void**)&pkf, g_kf);
    cudaGetSymbolAddress((void**)&pof, g_of);

    cudaFuncSetAttribute(pointwise_kernel,
                         cudaFuncAttributeMaxDynamicSharedMemorySize, PW_SMEM);

    // Forward rFFT along W (packed pairs, 16 pairs per block).
    rfft_rows_kernel<<<4096, 256>>>(x, pxf);
    rfft_rows_kernel<<<8192, 256>>>(w, pkf);

    // Forward FFT along H.
    fft_cols_kernel<-1><<<dim3(9, 512), 256>>>(pxf);
    fft_cols_kernel<-1><<<dim3(9, 1024), 256>>>(pkf);

    // Per-bin channel contraction on tensor cores.
    pointwise_kernel<<<4128, 256, PW_SMEM>>>(pxf, pkf, pof);

    // Inverse FFT along H + inverse rFFT along W.
    fft_cols_kernel<1><<<dim3(9, 512), 256>>>(pof);
    irfft_rows_kernel<<<4096, 256>>>(pof, out);
}

// round 10
// speedup vs baseline: 1.3876x; 1.1322x over previous
#include <cuda_runtime.h>
#include <cuda_fp16.h>
#include <mma.h>

#define TWO_PI 6.283185307179586f

using namespace nvcuda;

__device__ __forceinline__ float2 cmulf(float2 a, float2 b) {
    return make_float2(fmaf(a.x, b.x, -a.y * b.y), fmaf(a.x, b.y, a.y * b.x));
}
__device__ __forceinline__ float2 cadd(float2 a, float2 b) { return make_float2(a.x+b.x, a.y+b.y); }
__device__ __forceinline__ float2 csub(float2 a, float2 b) { return make_float2(a.x-b.x, a.y-b.y); }
__device__ __forceinline__ float2 mulc(float2 z, float cr, float ci) {
    return make_float2(fmaf(z.x, cr, -z.y * ci), fmaf(z.x, ci, z.y * cr));
}
__device__ __forceinline__ float2 h2f(__half2 h) { return __half22float2(h); }
__device__ __forceinline__ __half2 f2h(float2 f) { return __float22half2_rn(f); }

// Frequency-domain scratch in fp16.
__device__ __half2 g_xf[16908288];   // (16*32) x 256 x 129
__device__ __half2 g_kf[33816576];   // (32*32) x 256 x 129
__device__ __half2 g_of[16908288];   // (16*32) x 256 x 129

// ---------------------------------------------------------------------------
// 4-point / 16-point register DFTs.
// ---------------------------------------------------------------------------
template <int SIGN>
__device__ __forceinline__ void dft4(float2 a, float2 b, float2 c, float2 d,
                                     float2& y0, float2& y1, float2& y2, float2& y3)
{
    float2 t0 = cadd(a, c), t1 = csub(a, c);
    float2 t2 = cadd(b, d), t3 = csub(b, d);
    float2 w3 = (SIGN < 0) ? make_float2(t3.y, -t3.x) : make_float2(-t3.y, t3.x);
    y0 = cadd(t0, t2); y2 = csub(t0, t2);
    y1 = cadd(t1, w3); y3 = csub(t1, w3);
}

template <int SIGN>
__device__ __forceinline__ void dft16(float2 r[16])
{
    const float C1 = 0.9238795325112867f;
    const float S1 = 0.3826834323650898f;
    const float C2 = 0.7071067811865476f;
    const float sg = (float)SIGN;

    float2 A[16];
#pragma unroll
    for (int n2 = 0; n2 < 4; n2++)
        dft4<SIGN>(r[n2], r[4 + n2], r[8 + n2], r[12 + n2],
                   A[n2 * 4 + 0], A[n2 * 4 + 1], A[n2 * 4 + 2], A[n2 * 4 + 3]);

    A[4 + 1]  = mulc(A[4 + 1],  C1,  sg * S1);
    A[4 + 2]  = mulc(A[4 + 2],  C2,  sg * C2);
    A[4 + 3]  = mulc(A[4 + 3],  S1,  sg * C1);
    A[8 + 1]  = mulc(A[8 + 1],  C2,  sg * C2);
    A[8 + 2]  = (SIGN < 0) ? make_float2(A[8 + 2].y, -A[8 + 2].x)
                           : make_float2(-A[8 + 2].y, A[8 + 2].x);
    A[8 + 3]  = mulc(A[8 + 3], -C2,  sg * C2);
    A[12 + 1] = mulc(A[12 + 1], S1,  sg * C1);
    A[12 + 2] = mulc(A[12 + 2], -C2, sg * C2);
    A[12 + 3] = mulc(A[12 + 3], -C1, -sg * S1);

#pragma unroll
    for (int k1 = 0; k1 < 4; k1++)
        dft4<SIGN>(A[k1], A[4 + k1], A[8 + k1], A[12 + k1],
                   r[k1], r[k1 + 4], r[k1 + 8], r[k1 + 12]);
}

__device__ __forceinline__ int zpad(int k) { return k + (k >> 4); }

// ---------------------------------------------------------------------------
// Forward real FFT along W: 16 packed row-pairs per block, 16 threads per FFT.
// ---------------------------------------------------------------------------
__global__ void __launch_bounds__(256) rfft_rows_kernel(
    const float* __restrict__ in, __half2* __restrict__ out)
{
    __shared__ float2 tr[16][272];
    __shared__ float2 tw[256];
    const int t = threadIdx.x;
    const int f = t >> 4, j = t & 15;

    {
        float s, c;
        sincosf(-TWO_PI * (float)t / 256.0f, &s, &c);
        tw[t] = make_float2(c, s);
    }

    const long p = (long)blockIdx.x * 16 + f;
    const float* rp = in + p * 512;

    float2 r[16];
#pragma unroll
    for (int n1 = 0; n1 < 16; n1++)
        r[n1] = make_float2(rp[n1 * 16 + j], rp[256 + n1 * 16 + j]);

    dft16<-1>(r);
    __syncthreads();

#pragma unroll
    for (int k1 = 0; k1 < 16; k1++) {
        if (k1) r[k1] = cmulf(r[k1], tw[j * k1]);
        tr[f][k1 * 17 + j] = r[k1];
    }
    __syncthreads();

    float2 d[16];
#pragma unroll
    for (int n2 = 0; n2 < 16; n2++)
        d[n2] = tr[f][j * 17 + n2];

    dft16<-1>(d);
    __syncthreads();

#pragma unroll
    for (int k2 = 0; k2 < 16; k2++)
        tr[f][zpad(j + 16 * k2)] = d[k2];
    __syncthreads();

    __half2* o = out + p * 258;
#pragma unroll
    for (int k2 = 0; k2 < 9; k2++) {
        int k = j + 16 * k2;
        if (k <= 128) {
            float2 zk = tr[f][zpad(k)];
            float2 zm = tr[f][zpad((256 - k) & 255)];
            o[k]       = f2h(make_float2(0.5f * (zk.x + zm.x),  0.5f * (zk.y - zm.y)));
            o[129 + k] = f2h(make_float2(0.5f * (zk.y + zm.y), -0.5f * (zk.x - zm.x)));
        }
    }
}

// ---------------------------------------------------------------------------
// Complex FFT along H: 16x16 register Cooley-Tukey, 16 columns per block.
// ---------------------------------------------------------------------------
template <int SIGN>
__global__ void __launch_bounds__(256) fft_cols_kernel(__half2* __restrict__ data)
{
    __shared__ float2 tr[4096];
    __shared__ float2 tw[256];
    const int t = threadIdx.x;
    const int c = t & 15, j = t >> 4;

    {
        float s, cc;
        sincosf((float)SIGN * TWO_PI * (float)t / 256.0f, &s, &cc);
        tw[t] = make_float2(cc, s);
    }

    __half2* img = data + (size_t)blockIdx.y * 33024;
    const int col = blockIdx.x * 16 + c;
    const bool valid = (col < 129);

    float2 r[16];
#pragma unroll
    for (int n1 = 0; n1 < 16; n1++)
        r[n1] = valid ? h2f(img[(n1 * 16 + j) * 129 + col]) : make_float2(0.f, 0.f);

    dft16<SIGN>(r);
    __syncthreads();

#pragma unroll
    for (int k1 = 0; k1 < 16; k1++) {
        if (k1) r[k1] = cmulf(r[k1], tw[j * k1]);
        tr[(k1 * 16 + j) * 16 + c] = r[k1];
    }
    __syncthreads();

    float2 d[16];
#pragma unroll
    for (int n2 = 0; n2 < 16; n2++)
        d[n2] = tr[(j * 16 + n2) * 16 + c];

    dft16<SIGN>(d);

    if (valid) {
#pragma unroll
        for (int k2 = 0; k2 < 16; k2++)
            img[(j + 16 * k2) * 129 + col] = f2h(d[k2]);
    }
}

// ---------------------------------------------------------------------------
// Pointwise frequency contraction on tensor cores (WMMA m16n16k16, fp16 in /
// fp32 accumulate). 8 bins per block, warp <-> bin.
//
// Per bin f: OUT(16b x 32o) = X(16b x 32c) * K(32o x 32c)^T, complex via
//   out_r = Xr*Kr - Xi*Ki  (tmp accumulator + elementwise subtract)
//   out_i = Xr*Ki + Xi*Kr
//
// Smem: X planes (sxr/sxi, per-bin stride 648 halves, ldm 40) and K planes
// (skr/ski, per-bin stride 1288 halves, ldm 40). Output fp32 tiles ALIAS the
// K planes: bin fi's two 16x16 tiles (ldm 20, nt*320 floats) live exactly in
// bin fi's skr/ski slot (needs 2560B of 2576B). Safe because only warp fi
// touches bin fi, and the nt=0 output tile (bytes <1280) is written after the
// warp's nt=0 B-tile loads, while the nt=1 B tile lives at bytes >=1280.
// Total smem 61952 B -> 3 blocks/SM.
// ---------------------------------------------------------------------------
#define XSTR 648
#define KSTR 1288
#define OFF_SXI (8 * XSTR)                 // halves
#define OFF_SKR (16 * XSTR)
#define OFF_SKI (16 * XSTR + 8 * KSTR)
#define PW_SMEM ((16 * XSTR + 16 * KSTR) * 2)   // 61952 B

__global__ void __launch_bounds__(256, 3) pointwise_kernel(
    const __half2* __restrict__ xf, const __half2* __restrict__ kf,
    __half2* __restrict__ of)
{
    extern __shared__ char pwsm[];
    __half* sxr = (__half*)pwsm;
    __half* sxi = sxr + OFF_SXI;
    __half* skr = sxr + OFF_SKR;
    __half* ski = sxr + OFF_SKI;

    const int t = threadIdx.x;
    const long f0 = (long)blockIdx.x * 8;

    // Stage X: rows = b*32+c (512 rows), row-pairs packed into half2 stores.
    for (int idx = t; idx < 2048; idx += 256) {
        int rp2 = idx >> 3, fi = idx & 7;
        int row = rp2 * 2;
        __half2 v0 = xf[(size_t)row * 33024 + f0 + fi];
        __half2 v1 = xf[(size_t)(row + 1) * 33024 + f0 + fi];
        int b = row >> 5, c = row & 31;                 // c even
        int a = fi * XSTR + b * 40 + c;                 // even -> 4B aligned
        *(__half2*)(sxr + a) = __halves2half2(__low2half(v0),  __low2half(v1));
        *(__half2*)(sxi + a) = __halves2half2(__high2half(v0), __high2half(v1));
    }
    // Stage K: rows = o*32+c (1024 rows), row-pairs packed.
    for (int idx = t; idx < 4096; idx += 256) {
        int rp2 = idx >> 3, fi = idx & 7;
        int row = rp2 * 2;
        __half2 v0 = kf[(size_t)row * 33024 + f0 + fi];
        __half2 v1 = kf[(size_t)(row + 1) * 33024 + f0 + fi];
        int o = row >> 5, c = row & 31;
        int a = fi * KSTR + o * 40 + c;
        *(__half2*)(skr + a) = __halves2half2(__low2half(v0),  __low2half(v1));
        *(__half2*)(ski + a) = __halves2half2(__high2half(v0), __high2half(v1));
    }
    __syncthreads();

    // Each warp computes one bin's (16 x 32) complex GEMM.
    {
        const int fi = t >> 5;
        const __half* xr = sxr + fi * XSTR;
        const __half* xi = sxi + fi * XSTR;
        const __half* kr = skr + fi * KSTR;
        const __half* ki = ski + fi * KSTR;
        float* sorf = (float*)(skr + fi * KSTR);   // aliases this bin's K slot
        float* soif = (float*)(ski + fi * KSTR);

#pragma unroll
        for (int nt = 0; nt < 2; nt++) {
            wmma::fragment<wmma::accumulator, 16, 16, 16, float> accr, acci, tmpr;
            wmma::fill_fragment(accr, 0.0f);
            wmma::fill_fragment(acci, 0.0f);
            wmma::fill_fragment(tmpr, 0.0f);
#pragma unroll
            for (int kt = 0; kt < 2; kt++) {
                wmma::fragment<wmma::matrix_a, 16, 16, 16, __half, wmma::row_major> ar, ai;
                wmma::load_matrix_sync(ar, xr + kt * 16, 40);
                wmma::load_matrix_sync(ai, xi + kt * 16, 40);
                const int koff = (nt * 16) * 40 + kt * 16;
                wmma::fragment<wmma::matrix_b, 16, 16, 16, __half, wmma::col_major> br, bi;
                wmma::load_matrix_sync(br, kr + koff, 40);
                wmma::load_matrix_sync(bi, ki + koff, 40);
                wmma::mma_sync(accr, ar, br, accr);
                wmma::mma_sync(tmpr, ai, bi, tmpr);
                wmma::mma_sync(acci, ar, bi, acci);
                wmma::mma_sync(acci, ai, br, acci);
            }
#pragma unroll
            for (int e = 0; e < accr.num_elements; e++)
                accr.x[e] -= tmpr.x[e];
            // Store into the (now consumed) K slot for this nt tile.
            wmma::store_matrix_sync(sorf + nt * 320, accr, 20, wmma::mem_row_major);
            wmma::store_matrix_sync(soif + nt * 320, acci, 20, wmma::mem_row_major);
        }
    }
    __syncthreads();

    // Write out: rows = b*32+o (512 rows), two bins packed per STG.64.
    for (int idx = t; idx < 2048; idx += 256) {
        int row = idx >> 2, f2 = (idx & 3) * 2;         // bins f2, f2+1
        int b = row >> 5, o = row & 31;
        int addr = (o >> 4) * 320 + b * 20 + (o & 15);
        const float* s0r = (const float*)(skr + f2 * KSTR);
        const float* s0i = (const float*)(ski + f2 * KSTR);
        const float* s1r = (const float*)(skr + (f2 + 1) * KSTR);
        const float* s1i = (const float*)(ski + (f2 + 1) * KSTR);
        __half2 h0 = f2h(make_float2(s0r[addr], s0i[addr]));
        __half2 h1 = f2h(make_float2(s1r[addr], s1i[addr]));
        __half2* dst = of + (size_t)row * 33024 + f0 + f2;
        *(uint2*)dst = make_uint2(*reinterpret_cast<unsigned int*>(&h0),
                                  *reinterpret_cast<unsigned int*>(&h1));
    }
}

// ---------------------------------------------------------------------------
// Inverse real FFT along W: 16 row-pairs per block, register 16x16 FFT.
// ---------------------------------------------------------------------------
__global__ void __launch_bounds__(256) irfft_rows_kernel(
    const __half2* __restrict__ in, float* __restrict__ out)
{
    __shared__ float2 tr[16][272];
    __shared__ float2 tw[256];
    const int t = threadIdx.x;
    const int f = t >> 4, j = t & 15;

    {
        float s, c;
        sincosf(TWO_PI * (float)t / 256.0f, &s, &c);
        tw[t] = make_float2(c, s);
    }

    const long p = (long)blockIdx.x * 16 + f;
    const __half2* X0 = in + p * 258;
    const __half2* X1 = X0 + 129;

    float2 r[16];
#pragma unroll
    for (int a = 0; a < 16; a++) {
        int k = a * 16 + j;
        float2 av, bv;
        if (k <= 128) { av = h2f(X0[k]); bv = h2f(X1[k]); }
        else {
            float2 a0 = h2f(X0[256 - k]); av = make_float2(a0.x, -a0.y);
            float2 b0 = h2f(X1[256 - k]); bv = make_float2(b0.x, -b0.y);
        }
        r[a] = make_float2(av.x - bv.y, av.y + bv.x);
    }

    dft16<1>(r);
    __syncthreads();

#pragma unroll
    for (int k1 = 0; k1 < 16; k1++) {
        if (k1) r[k1] = cmulf(r[k1], tw[j * k1]);
        tr[f][k1 * 17 + j] = r[k1];
    }
    __syncthreads();

    float2 d[16];
#pragma unroll
    for (int n2 = 0; n2 < 16; n2++)
        d[n2] = tr[f][j * 17 + n2];

    dft16<1>(d);

    const float sc = 1.0f / 65536.0f;
    float* o = out + p * 512;
#pragma unroll
    for (int k2 = 0; k2 < 16; k2++) {
        int n = j + 16 * k2;
        o[n]       = d[k2].x * sc;
        o[256 + n] = d[k2].y * sc;
    }
}

// ---------------------------------------------------------------------------
extern "C" void kernel_launch(void* const* d_in, const int* in_sizes, int n_in,
                              void* d_out, int out_size)
{
    const float* x = (const float*)d_in[0];   // (16,32,256,256)
    const float* w = (const float*)d_in[1];   // (32,32,256,256)
    float* out = (float*)d_out;               // (16,32,256,256)

    __half2 *pxf, *pkf, *pof;
    cudaGetSymbolAddress((void**)&pxf, g_xf);
    cudaGetSymbolAddress((void**)&pkf, g_kf);
    cudaGetSymbolAddress((void**)&pof, g_of);

    cudaFuncSetAttribute(pointwise_kernel,
                         cudaFuncAttributeMaxDynamicSharedMemorySize, PW_SMEM);

    // Forward rFFT along W (packed pairs, 16 pairs per block).
    rfft_rows_kernel<<<4096, 256>>>(x, pxf);
    rfft_rows_kernel<<<8192, 256>>>(w, pkf);

    // Forward FFT along H.
    fft_cols_kernel<-1><<<dim3(9, 512), 256>>>(pxf);
    fft_cols_kernel<-1><<<dim3(9, 1024), 256>>>(pkf);

    // Per-bin channel contraction on tensor cores.
    pointwise_kernel<<<4128, 256, PW_SMEM>>>(pxf, pkf, pof);

    // Inverse FFT along H + inverse rFFT along W.
    fft_cols_kernel<1><<<dim3(9, 512), 256>>>(pof);
    irfft_rows_kernel<<<4096, 256>>>(pof, out);
}